// round 16
// baseline (speedup 1.0000x reference)
#include <cuda_runtime.h>

#define NN 1024
#define HH 128
#define NJB 8           // j-blocks of 128
#define GI_CTAS 96      // 16 mtiles x 6 ntiles, single wave (< 148 SMs)

// Device-global scratch (no allocation allowed)
__device__ float g_agg[NN * HH];          // atomically accumulated aggregate
__device__ float g_gi[NN * 3 * HH];       // gi = agg @ w_ih^T   [1024][384]
__device__ float g_gh[NN * 3 * HH];       // gh = nf  @ w_hh^T   [1024][384]
__device__ int   g_cnt;                   // grid-barrier counter (memset to 0)

// ---------------------------------------------------------------------------
// Kernel 1: barrier-free partial aggregation (frozen round-9 core; ~60us,
// regs 32, occ 73%, at the ~4.6 TB/s gated-scatter DRAM floor).
// ---------------------------------------------------------------------------
__global__ __launch_bounds__(256) void agg_kernel(
    const float* __restrict__ nf,
    const int*   __restrict__ adj,
    const float* __restrict__ T)
{
    const int ib   = blockIdx.x;
    const int jb   = blockIdx.y;
    const int tid  = threadIdx.x;
    const int lane = tid & 31;
    const int w    = tid >> 5;
    const int i    = ib * 8 + w;

    const float4* nf4 = (const float4*)nf;
    const float4* T4  = (const float4*)T;

    float4 a0 = make_float4(0.f,0.f,0.f,0.f);
    float4 a1 = make_float4(0.f,0.f,0.f,0.f);
    float4 a2 = make_float4(0.f,0.f,0.f,0.f);
    float4 a3 = make_float4(0.f,0.f,0.f,0.f);

    const int* adjrow = adj + (size_t)i * NN + jb * 128;

    #pragma unroll 1
    for (int c = 0; c < 4; c++) {
        const int av = __ldg(&adjrow[c * 32 + lane]);
        unsigned m = __ballot_sync(0xffffffffu, av != 0);
        int tot = __popc(m);

        const int    jbase   = jb * 128 + c * 32;
        const size_t rowbase = (size_t)i * NN + jbase;

        while (tot >= 4) {
            const int j0 = __ffs(m) - 1; m &= m - 1;
            const int j1 = __ffs(m) - 1; m &= m - 1;
            const int j2 = __ffs(m) - 1; m &= m - 1;
            const int j3 = __ffs(m) - 1; m &= m - 1;
            tot -= 4;
            float4 t0 = __ldcs(&T4[(rowbase + j0) * 32 + lane]);
            float4 t1 = __ldcs(&T4[(rowbase + j1) * 32 + lane]);
            float4 t2 = __ldcs(&T4[(rowbase + j2) * 32 + lane]);
            float4 t3 = __ldcs(&T4[(rowbase + j3) * 32 + lane]);
            float4 f0 = __ldg(&nf4[(size_t)(jbase + j0) * 32 + lane]);
            float4 f1 = __ldg(&nf4[(size_t)(jbase + j1) * 32 + lane]);
            float4 f2 = __ldg(&nf4[(size_t)(jbase + j2) * 32 + lane]);
            float4 f3 = __ldg(&nf4[(size_t)(jbase + j3) * 32 + lane]);
            a0.x += f0.x*t0.x; a0.y += f0.y*t0.y; a0.z += f0.z*t0.z; a0.w += f0.w*t0.w;
            a1.x += f1.x*t1.x; a1.y += f1.y*t1.y; a1.z += f1.z*t1.z; a1.w += f1.w*t1.w;
            a2.x += f2.x*t2.x; a2.y += f2.y*t2.y; a2.z += f2.z*t2.z; a2.w += f2.w*t2.w;
            a3.x += f3.x*t3.x; a3.y += f3.y*t3.y; a3.z += f3.z*t3.z; a3.w += f3.w*t3.w;
        }
        while (tot > 0) {
            const int j = __ffs(m) - 1; m &= m - 1; tot--;
            float4 t = __ldcs(&T4[(rowbase + j) * 32 + lane]);
            float4 f = __ldg(&nf4[(size_t)(jbase + j) * 32 + lane]);
            a0.x += f.x*t.x; a0.y += f.y*t.y; a0.z += f.z*t.z; a0.w += f.w*t.w;
        }
    }

    a0.x += a1.x + a2.x + a3.x;
    a0.y += a1.y + a2.y + a3.y;
    a0.z += a1.z + a2.z + a3.z;
    a0.w += a1.w + a2.w + a3.w;

    float* dst = g_agg + (size_t)i * HH + lane * 4;
    atomicAdd(dst + 0, a0.x);
    atomicAdd(dst + 1, a0.y);
    atomicAdd(dst + 2, a0.z);
    atomicAdd(dst + 3, a0.w);
}

// ---------------------------------------------------------------------------
// Shared GEMM tile body: computes a 64x64 tile of C = A[1024x128] @ W^T.
// ---------------------------------------------------------------------------
__device__ __forceinline__ void gemm_tile_64(
    const float4* __restrict__ A4, const float4* __restrict__ W4,
    float4* __restrict__ C4, int mt, int nt, int tid,
    float4 (*sA)[17], float4 (*sB)[17])
{
    const int tx = tid & 15;
    const int ty = tid >> 4;
    const int mbase = mt * 64;
    const int nbase = nt * 64;

    float c00=0,c01=0,c02=0,c03=0, c10=0,c11=0,c12=0,c13=0;
    float c20=0,c21=0,c22=0,c23=0, c30=0,c31=0,c32=0,c33=0;

    #pragma unroll
    for (int kb = 0; kb < 2; kb++) {
        #pragma unroll
        for (int e = tid; e < 64 * 16; e += 256) {
            const int m = e >> 4, kq = e & 15;
            sA[m][kq] = A4[(size_t)(mbase + m) * 32 + kb * 16 + kq];
        }
        #pragma unroll
        for (int e = tid; e < 64 * 16; e += 256) {
            const int n = e >> 4, kq = e & 15;
            sB[n][kq] = W4[(size_t)(nbase + n) * 32 + kb * 16 + kq];
        }
        __syncthreads();

        #pragma unroll
        for (int kq = 0; kq < 16; kq++) {
            const float4 a0 = sA[ty * 4 + 0][kq];
            const float4 a1 = sA[ty * 4 + 1][kq];
            const float4 a2 = sA[ty * 4 + 2][kq];
            const float4 a3 = sA[ty * 4 + 3][kq];
            const float4 b0 = sB[tx * 4 + 0][kq];
            const float4 b1 = sB[tx * 4 + 1][kq];
            const float4 b2 = sB[tx * 4 + 2][kq];
            const float4 b3 = sB[tx * 4 + 3][kq];

            c00 += a0.x*b0.x + a0.y*b0.y + a0.z*b0.z + a0.w*b0.w;
            c01 += a0.x*b1.x + a0.y*b1.y + a0.z*b1.z + a0.w*b1.w;
            c02 += a0.x*b2.x + a0.y*b2.y + a0.z*b2.z + a0.w*b2.w;
            c03 += a0.x*b3.x + a0.y*b3.y + a0.z*b3.z + a0.w*b3.w;
            c10 += a1.x*b0.x + a1.y*b0.y + a1.z*b0.z + a1.w*b0.w;
            c11 += a1.x*b1.x + a1.y*b1.y + a1.z*b1.z + a1.w*b1.w;
            c12 += a1.x*b2.x + a1.y*b2.y + a1.z*b2.z + a1.w*b2.w;
            c13 += a1.x*b3.x + a1.y*b3.y + a1.z*b3.z + a1.w*b3.w;
            c20 += a2.x*b0.x + a2.y*b0.y + a2.z*b0.z + a2.w*b0.w;
            c21 += a2.x*b1.x + a2.y*b1.y + a2.z*b1.z + a2.w*b1.w;
            c22 += a2.x*b2.x + a2.y*b2.y + a2.z*b2.z + a2.w*b2.w;
            c23 += a2.x*b3.x + a2.y*b3.y + a2.z*b3.z + a2.w*b3.w;
            c30 += a3.x*b0.x + a3.y*b0.y + a3.z*b0.z + a3.w*b0.w;
            c31 += a3.x*b1.x + a3.y*b1.y + a3.z*b1.z + a3.w*b1.w;
            c32 += a3.x*b2.x + a3.y*b2.y + a3.z*b2.z + a3.w*b2.w;
            c33 += a3.x*b3.x + a3.y*b3.y + a3.z*b3.z + a3.w*b3.w;
        }
        __syncthreads();
    }

    const int m0 = mbase + ty * 4;
    const int n4 = nt * 16 + tx;
    C4[(size_t)(m0 + 0) * 96 + n4] = make_float4(c00, c01, c02, c03);
    C4[(size_t)(m0 + 1) * 96 + n4] = make_float4(c10, c11, c12, c13);
    C4[(size_t)(m0 + 2) * 96 + n4] = make_float4(c20, c21, c22, c23);
    C4[(size_t)(m0 + 3) * 96 + n4] = make_float4(c30, c31, c32, c33);
}

// ---------------------------------------------------------------------------
// Kernel 2: gh GEMM (side stream, overlapped with agg).
// ---------------------------------------------------------------------------
__global__ __launch_bounds__(256) void gemm64_kernel(
    const float* __restrict__ A,
    const float* __restrict__ W,
    float*       __restrict__ C)
{
    __shared__ float4 sA[64][17];
    __shared__ float4 sB[64][17];
    gemm_tile_64((const float4*)A, (const float4*)W, (float4*)C,
                 blockIdx.x, blockIdx.y, threadIdx.x, sA, sB);
}

// ---------------------------------------------------------------------------
// Kernel 3: fused [gi GEMM -> software grid barrier -> GRU epilogue].
// 96 CTAs < 148 SMs => single wave, arrive+spin barrier is deadlock-free.
// ---------------------------------------------------------------------------
__global__ __launch_bounds__(256) void gi_ep_kernel(
    const float* __restrict__ wih,
    const float* __restrict__ nf,
    const float* __restrict__ bih,
    const float* __restrict__ bhh,
    float*       __restrict__ out)
{
    __shared__ float4 sA[64][17];
    __shared__ float4 sB[64][17];

    const int bx  = blockIdx.x;
    const int tid = threadIdx.x;

    gemm_tile_64((const float4*)g_agg, (const float4*)wih, (float4*)g_gi,
                 bx & 15, bx >> 4, tid, sA, sB);

    // ---- software grid barrier ----
    __threadfence();
    __syncthreads();
    if (tid == 0) {
        atomicAdd(&g_cnt, 1);
        while (((volatile int*)&g_cnt)[0] < GI_CTAS) { }
    }
    __syncthreads();
    __threadfence();

    // ---- GRU epilogue: 32768 float4 over 96 CTAs (L2-hot data) ----
    const float4* gi4 = (const float4*)g_gi;
    const float4* gh4 = (const float4*)g_gh;
    const float4* bi4 = (const float4*)bih;
    const float4* bh4 = (const float4*)bhh;

    for (int e = bx * 256 + tid; e < NN * 32; e += GI_CTAS * 256) {
        const int i  = e >> 5;
        const int hq = e & 31;
        const size_t row = (size_t)i * 96;

        const float4 ir = gi4[row + hq],      hr = gh4[row + hq];
        const float4 iz = gi4[row + 32 + hq], hz = gh4[row + 32 + hq];
        const float4 in_= gi4[row + 64 + hq], hn = gh4[row + 64 + hq];
        const float4 bir = bi4[hq],      bhr = bh4[hq];
        const float4 biz = bi4[32 + hq], bhz = bh4[32 + hq];
        const float4 bin = bi4[64 + hq], bhn = bh4[64 + hq];
        const float4 hp  = ((const float4*)nf)[e];

        float4 o;
        {
            float r = 1.f / (1.f + __expf(-(ir.x + hr.x + bir.x + bhr.x)));
            float z = 1.f / (1.f + __expf(-(iz.x + hz.x + biz.x + bhz.x)));
            float n = tanhf(in_.x + bin.x + r * (hn.x + bhn.x));
            o.x = (1.f - z) * n + z * hp.x;
        }
        {
            float r = 1.f / (1.f + __expf(-(ir.y + hr.y + bir.y + bhr.y)));
            float z = 1.f / (1.f + __expf(-(iz.y + hz.y + biz.y + bhz.y)));
            float n = tanhf(in_.y + bin.y + r * (hn.y + bhn.y));
            o.y = (1.f - z) * n + z * hp.y;
        }
        {
            float r = 1.f / (1.f + __expf(-(ir.z + hr.z + bir.z + bhr.z)));
            float z = 1.f / (1.f + __expf(-(iz.z + hz.z + biz.z + bhz.z)));
            float n = tanhf(in_.z + bin.z + r * (hn.z + bhn.z));
            o.z = (1.f - z) * n + z * hp.z;
        }
        {
            float r = 1.f / (1.f + __expf(-(ir.w + hr.w + bir.w + bhr.w)));
            float z = 1.f / (1.f + __expf(-(iz.w + hz.w + biz.w + bhz.w)));
            float n = tanhf(in_.w + bin.w + r * (hn.w + bhn.w));
            o.w = (1.f - z) * n + z * hp.w;
        }
        ((float4*)out)[e] = o;
    }
}

extern "C" void kernel_launch(void* const* d_in, const int* in_sizes, int n_in,
                              void* d_out, int out_size)
{
    const float* nf  = (const float*)d_in[0];
    const int*   adj = (const int*)  d_in[1];
    const float* T   = (const float*)d_in[2];
    const float* wih = (const float*)d_in[3];
    const float* whh = (const float*)d_in[4];
    const float* bih = (const float*)d_in[5];
    const float* bhh = (const float*)d_in[6];
    float* out = (float*)d_out;

    float* agg_ptr = nullptr;
    cudaGetSymbolAddress((void**)&agg_ptr, g_agg);
    float* gh_ptr = nullptr;
    cudaGetSymbolAddress((void**)&gh_ptr, g_gh);
    int* cnt_ptr = nullptr;
    cudaGetSymbolAddress((void**)&cnt_ptr, g_cnt);

    // Fresh fork/join handles each call (host-side only; no device memory).
    cudaStream_t s2;
    cudaEvent_t  ef, ej;
    cudaStreamCreateWithFlags(&s2, cudaStreamNonBlocking);
    cudaEventCreateWithFlags(&ef, cudaEventDisableTiming);
    cudaEventCreateWithFlags(&ej, cudaEventDisableTiming);

    // Main stream: zero the atomic accumulator + barrier counter.
    cudaMemsetAsync(agg_ptr, 0, (size_t)NN * HH * sizeof(float), 0);
    cudaMemsetAsync(cnt_ptr, 0, sizeof(int), 0);

    // Fork: gh GEMM (independent of agg) runs concurrently on s2.
    cudaEventRecord(ef, 0);
    cudaStreamWaitEvent(s2, ef, 0);
    gemm64_kernel<<<dim3(16, 6), 256, 0, s2>>>(nf, whh, gh_ptr);

    agg_kernel<<<dim3(NN / 8, NJB), 256>>>(nf, adj, T);

    // Join: fused gi+ep kernel needs agg (stream 0) and gh (s2).
    cudaEventRecord(ej, s2);
    cudaStreamWaitEvent(0, ej, 0);

    gi_ep_kernel<<<GI_CTAS, 256>>>(wih, nf, bih, bhh, out);
}

// round 17
// speedup vs baseline: 1.0770x; 1.0770x over previous
#include <cuda_runtime.h>

#define NN 1024
#define HH 128
#define NJB 8           // j-blocks of 128

// Device-global scratch (no allocation allowed)
__device__ float g_agg[NN * HH];          // atomically accumulated aggregate
__device__ float g_gh[NN * 3 * HH];       // gh = nf @ w_hh^T   [1024][384]

// ---------------------------------------------------------------------------
// Kernel 1: barrier-free partial aggregation (frozen round-9 core; ~60us,
// regs 32, occ 73%, at the ~4.6 TB/s gated-scatter DRAM floor).
// Output via atomicAdd into g_agg (zeroed by captured memset).
// ---------------------------------------------------------------------------
__global__ __launch_bounds__(256) void agg_kernel(
    const float* __restrict__ nf,
    const int*   __restrict__ adj,
    const float* __restrict__ T)
{
    const int ib   = blockIdx.x;
    const int jb   = blockIdx.y;
    const int tid  = threadIdx.x;
    const int lane = tid & 31;
    const int w    = tid >> 5;
    const int i    = ib * 8 + w;

    const float4* nf4 = (const float4*)nf;
    const float4* T4  = (const float4*)T;

    float4 a0 = make_float4(0.f,0.f,0.f,0.f);
    float4 a1 = make_float4(0.f,0.f,0.f,0.f);
    float4 a2 = make_float4(0.f,0.f,0.f,0.f);
    float4 a3 = make_float4(0.f,0.f,0.f,0.f);

    const int* adjrow = adj + (size_t)i * NN + jb * 128;

    #pragma unroll 1
    for (int c = 0; c < 4; c++) {
        const int av = __ldg(&adjrow[c * 32 + lane]);
        unsigned m = __ballot_sync(0xffffffffu, av != 0);
        int tot = __popc(m);

        const int    jbase   = jb * 128 + c * 32;
        const size_t rowbase = (size_t)i * NN + jbase;

        while (tot >= 4) {
            const int j0 = __ffs(m) - 1; m &= m - 1;
            const int j1 = __ffs(m) - 1; m &= m - 1;
            const int j2 = __ffs(m) - 1; m &= m - 1;
            const int j3 = __ffs(m) - 1; m &= m - 1;
            tot -= 4;
            float4 t0 = __ldcs(&T4[(rowbase + j0) * 32 + lane]);
            float4 t1 = __ldcs(&T4[(rowbase + j1) * 32 + lane]);
            float4 t2 = __ldcs(&T4[(rowbase + j2) * 32 + lane]);
            float4 t3 = __ldcs(&T4[(rowbase + j3) * 32 + lane]);
            float4 f0 = __ldg(&nf4[(size_t)(jbase + j0) * 32 + lane]);
            float4 f1 = __ldg(&nf4[(size_t)(jbase + j1) * 32 + lane]);
            float4 f2 = __ldg(&nf4[(size_t)(jbase + j2) * 32 + lane]);
            float4 f3 = __ldg(&nf4[(size_t)(jbase + j3) * 32 + lane]);
            a0.x += f0.x*t0.x; a0.y += f0.y*t0.y; a0.z += f0.z*t0.z; a0.w += f0.w*t0.w;
            a1.x += f1.x*t1.x; a1.y += f1.y*t1.y; a1.z += f1.z*t1.z; a1.w += f1.w*t1.w;
            a2.x += f2.x*t2.x; a2.y += f2.y*t2.y; a2.z += f2.z*t2.z; a2.w += f2.w*t2.w;
            a3.x += f3.x*t3.x; a3.y += f3.y*t3.y; a3.z += f3.z*t3.z; a3.w += f3.w*t3.w;
        }
        while (tot > 0) {
            const int j = __ffs(m) - 1; m &= m - 1; tot--;
            float4 t = __ldcs(&T4[(rowbase + j) * 32 + lane]);
            float4 f = __ldg(&nf4[(size_t)(jbase + j) * 32 + lane]);
            a0.x += f.x*t.x; a0.y += f.y*t.y; a0.z += f.z*t.z; a0.w += f.w*t.w;
        }
    }

    a0.x += a1.x + a2.x + a3.x;
    a0.y += a1.y + a2.y + a3.y;
    a0.z += a1.z + a2.z + a3.z;
    a0.w += a1.w + a2.w + a3.w;

    float* dst = g_agg + (size_t)i * HH + lane * 4;
    atomicAdd(dst + 0, a0.x);
    atomicAdd(dst + 1, a0.y);
    atomicAdd(dst + 2, a0.z);
    atomicAdd(dst + 3, a0.w);
}

// ---------------------------------------------------------------------------
// Kernel 2: gh GEMM (round-13 verbatim). g_gh = nf @ whh^T.
// Runs on a side stream, fully overlapped with the DRAM-bound agg kernel.
// ---------------------------------------------------------------------------
__global__ __launch_bounds__(256) void gemm64_kernel(
    const float* __restrict__ A,
    const float* __restrict__ W,
    float*       __restrict__ C)
{
    const int mt  = blockIdx.x;
    const int nt  = blockIdx.y;
    const int tid = threadIdx.x;
    const int tx  = tid & 15;
    const int ty  = tid >> 4;

    const float4* A4 = (const float4*)A;
    const float4* W4 = (const float4*)W;
    float4*       C4 = (float4*)C;

    __shared__ float4 sA[64][17];
    __shared__ float4 sB[64][17];

    const int mbase = mt * 64;
    const int nbase = nt * 64;

    float c00=0,c01=0,c02=0,c03=0, c10=0,c11=0,c12=0,c13=0;
    float c20=0,c21=0,c22=0,c23=0, c30=0,c31=0,c32=0,c33=0;

    #pragma unroll
    for (int kb = 0; kb < 2; kb++) {
        #pragma unroll
        for (int e = tid; e < 64 * 16; e += 256) {
            const int m = e >> 4, kq = e & 15;
            sA[m][kq] = A4[(size_t)(mbase + m) * 32 + kb * 16 + kq];
        }
        #pragma unroll
        for (int e = tid; e < 64 * 16; e += 256) {
            const int n = e >> 4, kq = e & 15;
            sB[n][kq] = W4[(size_t)(nbase + n) * 32 + kb * 16 + kq];
        }
        __syncthreads();

        #pragma unroll
        for (int kq = 0; kq < 16; kq++) {
            const float4 a0 = sA[ty * 4 + 0][kq];
            const float4 a1 = sA[ty * 4 + 1][kq];
            const float4 a2 = sA[ty * 4 + 2][kq];
            const float4 a3 = sA[ty * 4 + 3][kq];
            const float4 b0 = sB[tx * 4 + 0][kq];
            const float4 b1 = sB[tx * 4 + 1][kq];
            const float4 b2 = sB[tx * 4 + 2][kq];
            const float4 b3 = sB[tx * 4 + 3][kq];

            c00 += a0.x*b0.x + a0.y*b0.y + a0.z*b0.z + a0.w*b0.w;
            c01 += a0.x*b1.x + a0.y*b1.y + a0.z*b1.z + a0.w*b1.w;
            c02 += a0.x*b2.x + a0.y*b2.y + a0.z*b2.z + a0.w*b2.w;
            c03 += a0.x*b3.x + a0.y*b3.y + a0.z*b3.z + a0.w*b3.w;
            c10 += a1.x*b0.x + a1.y*b0.y + a1.z*b0.z + a1.w*b0.w;
            c11 += a1.x*b1.x + a1.y*b1.y + a1.z*b1.z + a1.w*b1.w;
            c12 += a1.x*b2.x + a1.y*b2.y + a1.z*b2.z + a1.w*b2.w;
            c13 += a1.x*b3.x + a1.y*b3.y + a1.z*b3.z + a1.w*b3.w;
            c20 += a2.x*b0.x + a2.y*b0.y + a2.z*b0.z + a2.w*b0.w;
            c21 += a2.x*b1.x + a2.y*b1.y + a2.z*b1.z + a2.w*b1.w;
            c22 += a2.x*b2.x + a2.y*b2.y + a2.z*b2.z + a2.w*b2.w;
            c23 += a2.x*b3.x + a2.y*b3.y + a2.z*b3.z + a2.w*b3.w;
            c30 += a3.x*b0.x + a3.y*b0.y + a3.z*b0.z + a3.w*b0.w;
            c31 += a3.x*b1.x + a3.y*b1.y + a3.z*b1.z + a3.w*b1.w;
            c32 += a3.x*b2.x + a3.y*b2.y + a3.z*b2.z + a3.w*b2.w;
            c33 += a3.x*b3.x + a3.y*b3.y + a3.z*b3.z + a3.w*b3.w;
        }
        __syncthreads();
    }

    const int m0 = mbase + ty * 4;
    const int n4 = nt * 16 + tx;
    C4[(size_t)(m0 + 0) * 96 + n4] = make_float4(c00, c01, c02, c03);
    C4[(size_t)(m0 + 1) * 96 + n4] = make_float4(c10, c11, c12, c13);
    C4[(size_t)(m0 + 2) * 96 + n4] = make_float4(c20, c21, c22, c23);
    C4[(size_t)(m0 + 3) * 96 + n4] = make_float4(c30, c31, c32, c33);
}

// ---------------------------------------------------------------------------
// Kernel 3: gate-triple fused [gi GEMM + GRU epilogue], NO barrier.
// grid 64 CTAs (mt 0..31 x ht 0..1), block 128 (tx 0..15, ty 0..7).
// CTA computes gi for rows [mt*32, +32) and h-cols [ht*64, +64) in ALL THREE
// gates (W rows g*128 + ht*64 + n). r/z/n land in this CTA's registers, so
// the epilogue for its (i,h) block is local: gh/nf/biases read from L2-hot
// globals, out written directly. g_gi never materializes.
// smem: sA[32][33] f4 + sB[3][64][33] f4 = 118 KB dynamic (1 CTA/SM).
// ---------------------------------------------------------------------------
__global__ __launch_bounds__(128) void gi_ep_kernel(
    const float* __restrict__ wih,
    const float* __restrict__ nf,
    const float* __restrict__ bih,
    const float* __restrict__ bhh,
    float*       __restrict__ out)
{
    extern __shared__ float4 dsm[];
    float4* sA = dsm;               // [32][33]
    float4* sB = dsm + 32 * 33;     // [3][64][33]

    const int bx  = blockIdx.x;
    const int mt  = bx & 31;        // 32 row-tiles of 32
    const int ht  = bx >> 5;        // 2 h-tiles of 64
    const int tid = threadIdx.x;
    const int tx  = tid & 15;       // 4 cols each
    const int ty  = tid >> 4;       // 0..7, 4 rows each

    const float4* A4 = (const float4*)g_agg;   // [1024][32] f4
    const float4* W4 = (const float4*)wih;     // [384][32] f4

    // Stage A (full K): 1024 f4, 8 per thread.
    #pragma unroll
    for (int e = tid; e < 32 * 32; e += 128) {
        const int m = e >> 5, kq = e & 31;
        sA[m * 33 + kq] = A4[(size_t)(mt * 32 + m) * 32 + kq];
    }
    // Stage B (full K, 3 gates): 6144 f4, 48 per thread.
    #pragma unroll 8
    for (int e = tid; e < 3 * 64 * 32; e += 128) {
        const int g  = e >> 11;          // /2048
        const int r  = e & 2047;
        const int n  = r >> 5, kq = r & 31;
        sB[g * 2112 + n * 33 + kq] = W4[(size_t)(g * 128 + ht * 64 + n) * 32 + kq];
    }
    __syncthreads();

    float acc[3][4][4];
    #pragma unroll
    for (int g = 0; g < 3; g++)
        #pragma unroll
        for (int r = 0; r < 4; r++)
            #pragma unroll
            for (int c = 0; c < 4; c++) acc[g][r][c] = 0.f;

    #pragma unroll 4
    for (int kq = 0; kq < 32; kq++) {
        float4 a[4];
        #pragma unroll
        for (int r = 0; r < 4; r++)
            a[r] = sA[(ty * 4 + r) * 33 + kq];

        #pragma unroll
        for (int g = 0; g < 3; g++) {
            #pragma unroll
            for (int c = 0; c < 4; c++) {
                const float4 b = sB[g * 2112 + (tx * 4 + c) * 33 + kq];
                #pragma unroll
                for (int r = 0; r < 4; r++) {
                    acc[g][r][c] += a[r].x*b.x + a[r].y*b.y
                                  + a[r].z*b.z + a[r].w*b.w;
                }
            }
        }
    }

    // ---- local GRU epilogue ----
    const float4* gh4 = (const float4*)g_gh;   // row stride 96 f4
    const float4* bi4 = (const float4*)bih;    // 96 f4
    const float4* bh4 = (const float4*)bhh;
    const int cf4 = ht * 16 + tx;              // f4 col within 32 (per gate)

    const float4 bir = bi4[cf4],      bhr = bh4[cf4];
    const float4 biz = bi4[32 + cf4], bhz = bh4[32 + cf4];
    const float4 bin = bi4[64 + cf4], bhn = bh4[64 + cf4];

    #pragma unroll
    for (int r = 0; r < 4; r++) {
        const int i = mt * 32 + ty * 4 + r;
        const size_t row = (size_t)i * 96;
        const float4 ghr = gh4[row + cf4];
        const float4 ghz = gh4[row + 32 + cf4];
        const float4 ghn = gh4[row + 64 + cf4];
        const float4 hp  = ((const float4*)nf)[(size_t)i * 32 + cf4];

        float4 o;
        {
            float rr = 1.f / (1.f + __expf(-(acc[0][r][0] + ghr.x + bir.x + bhr.x)));
            float zz = 1.f / (1.f + __expf(-(acc[1][r][0] + ghz.x + biz.x + bhz.x)));
            float nn = tanhf(acc[2][r][0] + bin.x + rr * (ghn.x + bhn.x));
            o.x = (1.f - zz) * nn + zz * hp.x;
        }
        {
            float rr = 1.f / (1.f + __expf(-(acc[0][r][1] + ghr.y + bir.y + bhr.y)));
            float zz = 1.f / (1.f + __expf(-(acc[1][r][1] + ghz.y + biz.y + bhz.y)));
            float nn = tanhf(acc[2][r][1] + bin.y + rr * (ghn.y + bhn.y));
            o.y = (1.f - zz) * nn + zz * hp.y;
        }
        {
            float rr = 1.f / (1.f + __expf(-(acc[0][r][2] + ghr.z + bir.z + bhr.z)));
            float zz = 1.f / (1.f + __expf(-(acc[1][r][2] + ghz.z + biz.z + bhz.z)));
            float nn = tanhf(acc[2][r][2] + bin.z + rr * (ghn.z + bhn.z));
            o.z = (1.f - zz) * nn + zz * hp.z;
        }
        {
            float rr = 1.f / (1.f + __expf(-(acc[0][r][3] + ghr.w + bir.w + bhr.w)));
            float zz = 1.f / (1.f + __expf(-(acc[1][r][3] + ghz.w + biz.w + bhz.w)));
            float nn = tanhf(acc[2][r][3] + bin.w + rr * (ghn.w + bhn.w));
            o.w = (1.f - zz) * nn + zz * hp.w;
        }
        ((float4*)out)[(size_t)i * 32 + cf4] = o;
    }
}

extern "C" void kernel_launch(void* const* d_in, const int* in_sizes, int n_in,
                              void* d_out, int out_size)
{
    const float* nf  = (const float*)d_in[0];
    const int*   adj = (const int*)  d_in[1];
    const float* T   = (const float*)d_in[2];
    const float* wih = (const float*)d_in[3];
    const float* whh = (const float*)d_in[4];
    const float* bih = (const float*)d_in[5];
    const float* bhh = (const float*)d_in[6];
    float* out = (float*)d_out;

    float* agg_ptr = nullptr;
    cudaGetSymbolAddress((void**)&agg_ptr, g_agg);
    float* gh_ptr = nullptr;
    cudaGetSymbolAddress((void**)&gh_ptr, g_gh);

    const int GIEP_SMEM = (32 * 33 + 3 * 64 * 33) * (int)sizeof(float4); // 118272
    cudaFuncSetAttribute(gi_ep_kernel,
                         cudaFuncAttributeMaxDynamicSharedMemorySize, GIEP_SMEM);

    // Fresh fork/join handles each call (host-side only; no device memory).
    cudaStream_t s2;
    cudaEvent_t  ef, ej;
    cudaStreamCreateWithFlags(&s2, cudaStreamNonBlocking);
    cudaEventCreateWithFlags(&ef, cudaEventDisableTiming);
    cudaEventCreateWithFlags(&ej, cudaEventDisableTiming);

    // Main stream: zero the atomic accumulator, then run agg.
    cudaMemsetAsync(agg_ptr, 0, (size_t)NN * HH * sizeof(float), 0);

    // Fork: gh GEMM (independent of agg) runs concurrently on s2.
    cudaEventRecord(ef, 0);
    cudaStreamWaitEvent(s2, ef, 0);
    gemm64_kernel<<<dim3(16, 6), 256, 0, s2>>>(nf, whh, gh_ptr);

    agg_kernel<<<dim3(NN / 8, NJB), 256>>>(nf, adj, T);

    // Join: fused gi+ep kernel needs agg (stream 0) and gh (s2).
    cudaEventRecord(ej, s2);
    cudaStreamWaitEvent(0, ej, 0);

    gi_ep_kernel<<<64, 128, GIEP_SMEM>>>(wih, nf, bih, bhh, out);
}